// round 6
// baseline (speedup 1.0000x reference)
#include <cuda_runtime.h>
#include <math.h>

#define NN 20000
#define EE 320000
#define FF 128
#define TF3 384
#define RB 20
#define PI_F 3.14159265358979323846f

// Scratch (static device globals; no allocation in kernel_launch)
__device__ __align__(16) float g_P[(size_t)NN * 512];
__device__ int g_off[NN + 1];
__device__ int g_cnt[NN];
__device__ int g_cur[NN];
__device__ int g_srcs[EE];

// ---------------------------------------------------------------------------
// Per-node precompute:
//   h      = silu(node_s @ W1 + b1)
//   s_out  = h @ W2 + b2                   (only cols [0,128) and [256,384))
//   filt   = rbf(edge_dis[n]) @ Wf + bf    (same cols)
//   w      = s_out * filt * ccut(edge_dis[n])
//   P[n][0:384]   = node_vec[n,f,c] * w_gate[f]   (f-major, 3 per f)
//   P[n][384:512] = w_scalar[f]
// Tile: 64 nodes/block, 256 threads (16x16), 4m x 8f register microtile.
// ---------------------------------------------------------------------------
__global__ __launch_bounds__(256) void precompute_kernel(
    const float* __restrict__ node_s,
    const float* __restrict__ node_vec,
    const float* __restrict__ edge_dis,
    const float* __restrict__ W1, const float* __restrict__ b1,
    const float* __restrict__ W2, const float* __restrict__ b2,
    const float* __restrict__ Wf, const float* __restrict__ bf)
{
    __shared__ float Ssh[64][FF + 1];   // node_s tile, reused for h
    __shared__ float Rsh[64][RB];       // rbf features
    __shared__ float Csh[64];           // cosine cutoff

    const int t = threadIdx.x;
    const int n0 = blockIdx.x * 64;

    // RBF + cutoff
    for (int i = t; i < 64 * RB; i += 256) {
        int m = i / RB, k = i - m * RB;
        int node = n0 + m;
        float d = (node < NN) ? edge_dis[node] : 1.0f;
        Rsh[m][k] = sinf((float)(k + 1) * (PI_F / 5.0f) * d) / d;
        if (k == 0)
            Csh[m] = (d <= 5.0f) ? 0.5f * (cosf(PI_F * d * 0.2f) + 1.0f) : 0.0f;
    }
    // Load node_s tile
    for (int i = t; i < 64 * FF; i += 256) {
        int m = i >> 7, c = i & (FF - 1);
        int node = n0 + m;
        Ssh[m][c] = (node < NN) ? node_s[(size_t)node * FF + c] : 0.0f;
    }
    __syncthreads();

    const int tx = t & 15, ty = t >> 4;
    const int mb = ty * 4;
    const int fb = tx * 8;

    // ---- GEMM1: h = silu(S @ W1 + b1) ----
    float acc[4][8];
    #pragma unroll
    for (int a = 0; a < 4; a++)
        #pragma unroll
        for (int i = 0; i < 8; i++) acc[a][i] = 0.0f;

    #pragma unroll 4
    for (int k = 0; k < FF; k++) {
        float4 wa = __ldg((const float4*)(W1 + (size_t)k * FF + fb));
        float4 wb = __ldg((const float4*)(W1 + (size_t)k * FF + fb + 4));
        float w[8] = {wa.x, wa.y, wa.z, wa.w, wb.x, wb.y, wb.z, wb.w};
        #pragma unroll
        for (int a = 0; a < 4; a++) {
            float s = Ssh[mb + a][k];
            #pragma unroll
            for (int i = 0; i < 8; i++) acc[a][i] += s * w[i];
        }
    }
    {
        float4 ba = __ldg((const float4*)(b1 + fb));
        float4 bb = __ldg((const float4*)(b1 + fb + 4));
        float bv[8] = {ba.x, ba.y, ba.z, ba.w, bb.x, bb.y, bb.z, bb.w};
        __syncthreads();  // all reads of Ssh done before overwrite
        #pragma unroll
        for (int a = 0; a < 4; a++)
            #pragma unroll
            for (int i = 0; i < 8; i++) {
                float x = acc[a][i] + bv[i];
                Ssh[mb + a][fb + i] = x / (1.0f + __expf(-x));
            }
    }
    __syncthreads();

    // ---- GEMM2 + filter epilogue; two passes: gate cols [0,128), scalar [256,384) ----
    #pragma unroll
    for (int p = 0; p < 2; p++) {
        const int jb = p ? 256 : 0;

        float a2[4][8];
        #pragma unroll
        for (int a = 0; a < 4; a++)
            #pragma unroll
            for (int i = 0; i < 8; i++) a2[a][i] = 0.0f;

        #pragma unroll 4
        for (int k = 0; k < FF; k++) {
            float4 wa = __ldg((const float4*)(W2 + (size_t)k * TF3 + jb + fb));
            float4 wb = __ldg((const float4*)(W2 + (size_t)k * TF3 + jb + fb + 4));
            float w[8] = {wa.x, wa.y, wa.z, wa.w, wb.x, wb.y, wb.z, wb.w};
            #pragma unroll
            for (int a = 0; a < 4; a++) {
                float h = Ssh[mb + a][k];
                #pragma unroll
                for (int i = 0; i < 8; i++) a2[a][i] += h * w[i];
            }
        }

        // filt[m][j] = bf[j] + sum_k rbf[m][k] * Wf[k][j]
        float flt[4][8];
        {
            float4 ba = __ldg((const float4*)(bf + jb + fb));
            float4 bb = __ldg((const float4*)(bf + jb + fb + 4));
            float bv[8] = {ba.x, ba.y, ba.z, ba.w, bb.x, bb.y, bb.z, bb.w};
            #pragma unroll
            for (int a = 0; a < 4; a++)
                #pragma unroll
                for (int i = 0; i < 8; i++) flt[a][i] = bv[i];
        }
        #pragma unroll
        for (int k = 0; k < RB; k++) {
            float4 wa = __ldg((const float4*)(Wf + (size_t)k * TF3 + jb + fb));
            float4 wb = __ldg((const float4*)(Wf + (size_t)k * TF3 + jb + fb + 4));
            float w[8] = {wa.x, wa.y, wa.z, wa.w, wb.x, wb.y, wb.z, wb.w};
            #pragma unroll
            for (int a = 0; a < 4; a++) {
                float r = Rsh[mb + a][k];
                #pragma unroll
                for (int i = 0; i < 8; i++) flt[a][i] += r * w[i];
            }
        }

        float4 b2a = __ldg((const float4*)(b2 + jb + fb));
        float4 b2b = __ldg((const float4*)(b2 + jb + fb + 4));
        float bv[8] = {b2a.x, b2a.y, b2a.z, b2a.w, b2b.x, b2b.y, b2b.z, b2b.w};

        #pragma unroll
        for (int a = 0; a < 4; a++) {
            int node = n0 + mb + a;
            if (node >= NN) continue;
            float cc = Csh[mb + a];
            float w[8];
            #pragma unroll
            for (int i = 0; i < 8; i++)
                w[i] = (a2[a][i] + bv[i]) * flt[a][i] * cc;

            if (p == 0) {
                const float* nv = node_vec + (size_t)node * TF3 + fb * 3;
                float*       Pp = g_P + (size_t)node * 512 + fb * 3;
                #pragma unroll
                for (int i = 0; i < 8; i++) {
                    #pragma unroll
                    for (int c = 0; c < 3; c++)
                        Pp[i * 3 + c] = nv[i * 3 + c] * w[i];
                }
            } else {
                float* Pp = g_P + (size_t)node * 512 + 384 + fb;
                #pragma unroll
                for (int i = 0; i < 8; i++) Pp[i] = w[i];
            }
        }
    }
}

// ---------------------------------------------------------------------------
// CSR build: zero counts -> histogram by dst -> exclusive scan -> fill srcs
// ---------------------------------------------------------------------------
__global__ void zero_kernel() {
    int i = blockIdx.x * blockDim.x + threadIdx.x;
    if (i < NN) g_cnt[i] = 0;
}

__global__ void hist_kernel(const int* __restrict__ edge) {
    int e = blockIdx.x * blockDim.x + threadIdx.x;
    if (e < EE) atomicAdd(&g_cnt[edge[2 * e]], 1);
}

__global__ __launch_bounds__(1024) void scan_kernel() {
    __shared__ int sh[1024];
    __shared__ int carry_sh;
    int t = threadIdx.x;
    if (t == 0) carry_sh = 0;
    __syncthreads();
    for (int base = 0; base < NN; base += 1024) {
        int idx = base + t;
        int x = (idx < NN) ? g_cnt[idx] : 0;
        sh[t] = x;
        __syncthreads();
        for (int off = 1; off < 1024; off <<= 1) {
            int v = (t >= off) ? sh[t - off] : 0;
            __syncthreads();
            sh[t] += v;
            __syncthreads();
        }
        int incl = sh[t];
        int c = carry_sh;
        if (idx < NN) {
            int ex = c + incl - x;
            g_off[idx] = ex;
            g_cur[idx] = ex;
        }
        __syncthreads();
        if (t == 1023) carry_sh = c + sh[1023];
        __syncthreads();
    }
    if (t == 0) g_off[NN] = carry_sh;
}

__global__ void fill_kernel(const int* __restrict__ edge) {
    int e = blockIdx.x * blockDim.x + threadIdx.x;
    if (e < EE) {
        int dst = edge[2 * e];
        int src = edge[2 * e + 1];
        int pos = atomicAdd(&g_cur[dst], 1);
        g_srcs[pos] = src;
    }
}

// ---------------------------------------------------------------------------
// Gather: one block (128 threads) per dst node. Each thread owns one float4
// of the 512-float message row; sums P[src] over the node's incoming edges,
// adds the residual base, writes the final output.
// Output layout: [0, N*384)  = node_vec + temp_vec ; [N*384, ...) = node_s + temp_s
// ---------------------------------------------------------------------------
__global__ __launch_bounds__(128) void gather_kernel(
    const float* __restrict__ node_s,
    const float* __restrict__ node_vec,
    float* __restrict__ out)
{
    const int n = blockIdx.x;
    const int t = threadIdx.x;
    const int beg = g_off[n];
    const int end = g_off[n + 1];
    const float4* __restrict__ P4 = (const float4*)g_P;

    float4 acc = make_float4(0.f, 0.f, 0.f, 0.f);

    int i = beg;
    for (; i + 4 <= end; i += 4) {
        int s0 = g_srcs[i + 0];
        int s1 = g_srcs[i + 1];
        int s2 = g_srcs[i + 2];
        int s3 = g_srcs[i + 3];
        float4 v0 = __ldg(P4 + (size_t)s0 * 128 + t);
        float4 v1 = __ldg(P4 + (size_t)s1 * 128 + t);
        float4 v2 = __ldg(P4 + (size_t)s2 * 128 + t);
        float4 v3 = __ldg(P4 + (size_t)s3 * 128 + t);
        acc.x += (v0.x + v1.x) + (v2.x + v3.x);
        acc.y += (v0.y + v1.y) + (v2.y + v3.y);
        acc.z += (v0.z + v1.z) + (v2.z + v3.z);
        acc.w += (v0.w + v1.w) + (v2.w + v3.w);
    }
    for (; i < end; i++) {
        int s = g_srcs[i];
        float4 v = __ldg(P4 + (size_t)s * 128 + t);
        acc.x += v.x; acc.y += v.y; acc.z += v.z; acc.w += v.w;
    }

    const int pos = t * 4;
    if (pos < 384) {
        float4 b = *(const float4*)(node_vec + (size_t)n * 384 + pos);
        float4 r = make_float4(b.x + acc.x, b.y + acc.y, b.z + acc.z, b.w + acc.w);
        *(float4*)(out + (size_t)n * 384 + pos) = r;
    } else {
        int q = pos - 384;
        float4 b = *(const float4*)(node_s + (size_t)n * 128 + q);
        float4 r = make_float4(b.x + acc.x, b.y + acc.y, b.z + acc.z, b.w + acc.w);
        *(float4*)(out + (size_t)NN * 384 + (size_t)n * 128 + q) = r;
    }
}

// ---------------------------------------------------------------------------
extern "C" void kernel_launch(void* const* d_in, const int* in_sizes, int n_in,
                              void* d_out, int out_size)
{
    const float* node_s   = (const float*)d_in[0];
    const float* node_vec = (const float*)d_in[1];
    const int*   edge     = (const int*)d_in[2];
    // d_in[3] = edge_difference (unused by the reference)
    const float* edge_dis = (const float*)d_in[4];
    const float* W1 = (const float*)d_in[5];
    const float* b1 = (const float*)d_in[6];
    const float* W2 = (const float*)d_in[7];
    const float* b2 = (const float*)d_in[8];
    const float* Wf = (const float*)d_in[9];
    const float* bf = (const float*)d_in[10];
    float* out = (float*)d_out;

    // CSR build
    zero_kernel<<<(NN + 255) / 256, 256>>>();
    hist_kernel<<<(EE + 255) / 256, 256>>>(edge);
    scan_kernel<<<1, 1024>>>();
    fill_kernel<<<(EE + 255) / 256, 256>>>(edge);

    // Per-node message precompute
    precompute_kernel<<<(NN + 63) / 64, 256>>>(node_s, node_vec, edge_dis,
                                               W1, b1, W2, b2, Wf, bf);

    // Scatter-as-gather + residual add
    gather_kernel<<<NN, 128>>>(node_s, node_vec, out);
}